// round 1
// baseline (speedup 1.0000x reference)
#include <cuda_runtime.h>

// ConformalMetric: R = -2*exp(-2*Phi) * (lap(Phi) + 2*|grad(Phi)|^2)
// Phi = phi_pos - lambda*phi_neg, edge-clamped 6-point stencil, h=1.
// Shape (B,H,W,D) = (4,128,128,128), D contiguous.

#define Bn 4
#define Hn 128
#define Wn 128
#define Dn 128

__global__ __launch_bounds__(256, 4) void conformal_kernel(
    const float* __restrict__ pos,
    const float* __restrict__ neg,
    const float* __restrict__ lam_p,
    float* __restrict__ out)
{
    const float lam = __ldg(lam_p);

    const int d = threadIdx.x * 4;                 // 0..124, step 4
    const int w = blockIdx.x * 8 + threadIdx.y;    // 0..127
    const int h = blockIdx.y;                      // 0..127
    const int b = blockIdx.z;                      // 0..3

    const int hm = (h > 0)      ? h - 1 : 0;
    const int hp = (h < Hn - 1) ? h + 1 : Hn - 1;
    const int wm = (w > 0)      ? w - 1 : 0;
    const int wp = (w < Wn - 1) ? w + 1 : Wn - 1;

    const int row    = ((b * Hn + h)  * Wn + w)  * Dn;
    const int row_hm = ((b * Hn + hm) * Wn + w)  * Dn;
    const int row_hp = ((b * Hn + hp) * Wn + w)  * Dn;
    const int row_wm = ((b * Hn + h)  * Wn + wm) * Dn;
    const int row_wp = ((b * Hn + h)  * Wn + wp) * Dn;
    const int idx = row + d;

    auto ldphi4 = [&](int i) -> float4 {
        float4 p = *reinterpret_cast<const float4*>(pos + i);
        float4 n = *reinterpret_cast<const float4*>(neg + i);
        return make_float4(fmaf(-lam, n.x, p.x),
                           fmaf(-lam, n.y, p.y),
                           fmaf(-lam, n.z, p.z),
                           fmaf(-lam, n.w, p.w));
    };

    const float4 C  = ldphi4(idx);
    const float4 XM = ldphi4(row_hm + d);
    const float4 XP = ldphi4(row_hp + d);
    const float4 YM = ldphi4(row_wm + d);
    const float4 YP = ldphi4(row_wp + d);

    // D-axis neighbors: interior from the center vector, edges via scalar loads
    // (clamped at the physical boundary d=0 / d=Dn-1).
    float zm0 = (d == 0)      ? C.x : fmaf(-lam, neg[idx - 1], pos[idx - 1]);
    float zp3 = (d + 4 >= Dn) ? C.w : fmaf(-lam, neg[idx + 4], pos[idx + 4]);

    float c_[4]  = {C.x,  C.y,  C.z,  C.w};
    float xm_[4] = {XM.x, XM.y, XM.z, XM.w};
    float xp_[4] = {XP.x, XP.y, XP.z, XP.w};
    float ym_[4] = {YM.x, YM.y, YM.z, YM.w};
    float yp_[4] = {YP.x, YP.y, YP.z, YP.w};
    float zm_[4] = {zm0,  C.x,  C.y,  C.z};
    float zp_[4] = {C.y,  C.z,  C.w,  zp3};

    float r_[4];
#pragma unroll
    for (int j = 0; j < 4; ++j) {
        const float c  = c_[j];
        const float xm = xm_[j], xp = xp_[j];
        const float ym = ym_[j], yp = yp_[j];
        const float zm = zm_[j], zp = zp_[j];

        const float gx = (xp - xm) * 0.5f;
        const float gy = (yp - ym) * 0.5f;
        const float gz = (zp - zm) * 0.5f;
        const float grad_sq = fmaf(gx, gx, fmaf(gy, gy, gz * gz));
        const float lap = (xp + xm) + (yp + ym) + (zp + zm) - 6.0f * c;
        // R = -2 * exp(-2c) * (lap + 2*grad_sq)
        r_[j] = -2.0f * __expf(-2.0f * c) * fmaf(2.0f, grad_sq, lap);
    }

    *reinterpret_cast<float4*>(out + idx) = make_float4(r_[0], r_[1], r_[2], r_[3]);
}

extern "C" void kernel_launch(void* const* d_in, const int* in_sizes, int n_in,
                              void* d_out, int out_size)
{
    const float* pos = (const float*)d_in[0];  // phi_positive (B,H,W,D) f32
    const float* neg = (const float*)d_in[1];  // phi_negative (B,H,W,D) f32
    const float* lam = (const float*)d_in[2];  // lambda_repulsion (1,) f32
    float* out = (float*)d_out;

    dim3 block(32, 8, 1);                 // 32 float4 lanes over D, 8 W-rows
    dim3 grid(Wn / 8, Hn, Bn);            // (16, 128, 4)
    conformal_kernel<<<grid, block>>>(pos, neg, lam, out);
}

// round 2
// speedup vs baseline: 1.0721x; 1.0721x over previous
#include <cuda_runtime.h>

// ConformalMetric: R = -2*exp(-2*Phi) * (lap(Phi) + 2*|grad(Phi)|^2)
// Phi = phi_pos - lambda*phi_neg, edge-clamped 6-point stencil, h=1.
// Shape (B,H,W,D) = (4,128,128,128), D contiguous.
//
// Strategy: H-march with rolling registers (Phi at h-1,h,h+1 per thread),
// W-neighbor exchange via double-buffered smem plane, D-neighbors via warp
// shuffle (one warp's 32 float4 lanes cover D=128 exactly).
// Global loads per 4 outputs: 2x LDG.128 (unique-only) + slab-edge halo.

#define Bn 4
#define Hn 128
#define Wn 128
#define Dn 128
#define WSLAB 8     // W rows per block
#define CH 16       // H planes marched per block

__global__ __launch_bounds__(256, 4) void conformal_march(
    const float* __restrict__ pos,
    const float* __restrict__ neg,
    const float* __restrict__ lam_p,
    float* __restrict__ out)
{
    // double-buffered Phi plane: WSLAB center rows + 2 halo rows, 32 float4 each
    __shared__ float4 S[2][WSLAB + 2][32];

    const float lam = __ldg(lam_p);

    const int tx = threadIdx.x;            // 0..31 -> d4 lane
    const int ty = threadIdx.y;            // 0..WSLAB-1 -> w row
    const int b  = blockIdx.z;
    const int h0 = blockIdx.y * CH;
    const int w  = blockIdx.x * WSLAB + ty;

    const int wm = (w > 0)      ? w - 1 : 0;        // used by ty==0 only
    const int wp = (w < Wn - 1) ? w + 1 : Wn - 1;   // used by ty==WSLAB-1 only

    const long base_b = (long)b * Hn * Wn * Dn;

    auto ldphi = [&](int hh, int ww) -> float4 {
        const long i = base_b + ((long)hh * Wn + ww) * Dn + tx * 4;
        float4 p = *reinterpret_cast<const float4*>(pos + i);
        float4 n = *reinterpret_cast<const float4*>(neg + i);
        return make_float4(fmaf(-lam, n.x, p.x),
                           fmaf(-lam, n.y, p.y),
                           fmaf(-lam, n.z, p.z),
                           fmaf(-lam, n.w, p.w));
    };

    // ── prologue: rows h0-1 (clamped) and h0, publish plane h0 to smem ──
    const int hm0 = (h0 > 0) ? h0 - 1 : 0;
    float4 Cm = ldphi(hm0, w);   // Phi(h-1)
    float4 Cc = ldphi(h0,  w);   // Phi(h)

    S[0][ty + 1][tx] = Cc;
    if (ty == 0)         S[0][0][tx]         = ldphi(h0, wm);
    if (ty == WSLAB - 1) S[0][WSLAB + 1][tx] = ldphi(h0, wp);
    __syncthreads();

    int cur = 0;
#pragma unroll 4
    for (int hh = 0; hh < CH; ++hh) {
        const int h  = h0 + hh;
        const int hp = (h < Hn - 1) ? h + 1 : Hn - 1;

        // issue next-plane loads first (overlap with smem reads + compute)
        float4 Cp = ldphi(hp, w);                       // Phi(h+1)
        float4 Hm = make_float4(0.f, 0.f, 0.f, 0.f);
        float4 Hp = make_float4(0.f, 0.f, 0.f, 0.f);
        if (ty == 0)         Hm = ldphi(hp, wm);
        if (ty == WSLAB - 1) Hp = ldphi(hp, wp);

        // W-neighbors of plane h from smem
        const float4 YM = S[cur][ty][tx];
        const float4 YP = S[cur][ty + 2][tx];

        // D-neighbors of plane h via warp shuffle (warp spans full D row)
        float zm0 = __shfl_up_sync(0xffffffffu,  Cc.w, 1);
        float zp3 = __shfl_down_sync(0xffffffffu, Cc.x, 1);
        if (tx == 0)  zm0 = Cc.x;   // edge clamp d=0
        if (tx == 31) zp3 = Cc.w;   // edge clamp d=Dn-1

        const float c_[4]  = {Cc.x, Cc.y, Cc.z, Cc.w};
        const float xm_[4] = {Cm.x, Cm.y, Cm.z, Cm.w};
        const float xp_[4] = {Cp.x, Cp.y, Cp.z, Cp.w};
        const float ym_[4] = {YM.x, YM.y, YM.z, YM.w};
        const float yp_[4] = {YP.x, YP.y, YP.z, YP.w};
        const float zm_[4] = {zm0,  Cc.x, Cc.y, Cc.z};
        const float zp_[4] = {Cc.y, Cc.z, Cc.w, zp3};

        float r_[4];
#pragma unroll
        for (int j = 0; j < 4; ++j) {
            const float c  = c_[j];
            const float gx = (xp_[j] - xm_[j]) * 0.5f;
            const float gy = (yp_[j] - ym_[j]) * 0.5f;
            const float gz = (zp_[j] - zm_[j]) * 0.5f;
            const float grad_sq = fmaf(gx, gx, fmaf(gy, gy, gz * gz));
            const float lap = (xp_[j] + xm_[j]) + (yp_[j] + ym_[j])
                            + (zp_[j] + zm_[j]) - 6.0f * c;
            r_[j] = -2.0f * __expf(-2.0f * c) * fmaf(2.0f, grad_sq, lap);
        }

        const long oidx = base_b + ((long)h * Wn + w) * Dn + tx * 4;
        *reinterpret_cast<float4*>(out + oidx) =
            make_float4(r_[0], r_[1], r_[2], r_[3]);

        // publish plane h+1 into the other buffer
        const int nxt = cur ^ 1;
        S[nxt][ty + 1][tx] = Cp;
        if (ty == 0)         S[nxt][0][tx]         = Hm;
        if (ty == WSLAB - 1) S[nxt][WSLAB + 1][tx] = Hp;
        __syncthreads();

        Cm = Cc; Cc = Cp; cur = nxt;
    }
}

extern "C" void kernel_launch(void* const* d_in, const int* in_sizes, int n_in,
                              void* d_out, int out_size)
{
    const float* pos = (const float*)d_in[0];  // phi_positive (B,H,W,D) f32
    const float* neg = (const float*)d_in[1];  // phi_negative (B,H,W,D) f32
    const float* lam = (const float*)d_in[2];  // lambda_repulsion (1,) f32
    float* out = (float*)d_out;

    dim3 block(32, WSLAB, 1);                  // 256 threads
    dim3 grid(Wn / WSLAB, Hn / CH, Bn);        // (16, 8, 4) = 512 blocks
    conformal_march<<<grid, block>>>(pos, neg, lam, out);
}

// round 3
// speedup vs baseline: 1.4324x; 1.3361x over previous
#include <cuda_runtime.h>

// ConformalMetric: R = -2*exp(-2*Phi) * (lap(Phi) + 2*|grad(Phi)|^2)
// Phi = phi_pos - lambda*phi_neg, edge-clamped 6-point stencil, h=1.
// Shape (B,H,W,D) = (4,128,128,128), D contiguous.
//
// Round-3 strategy: barrier-free H-march. Rolling registers hold Phi(h-1),
// Phi(h); per step load Phi(h+1,w) + Phi(h,w±1) directly from global
// (w±1 are L1/L2 hits from neighbor threads' center loads). D-neighbors via
// warp shuffle (32 float4 lanes cover D=128). No smem, no __syncthreads ->
// every load independent, deep MLP. Streaming stores keep inputs L2-resident.

#define Bn 4
#define Hn 128
#define Wn 128
#define Dn 128
#define WSLAB 8     // W rows per block
#define CH 8        // H planes marched per block

__global__ __launch_bounds__(256, 5) void conformal_march2(
    const float* __restrict__ pos,
    const float* __restrict__ neg,
    const float* __restrict__ lam_p,
    float* __restrict__ out)
{
    const float lam = __ldg(lam_p);

    const int tx = threadIdx.x;            // 0..31 -> d4 lane
    const int ty = threadIdx.y;            // 0..WSLAB-1 -> w row
    const int b  = blockIdx.z;
    const int h0 = blockIdx.y * CH;
    const int w  = blockIdx.x * WSLAB + ty;

    const int wm = (w > 0)      ? w - 1 : 0;
    const int wp = (w < Wn - 1) ? w + 1 : Wn - 1;

    const int base_b = b * Hn * Wn * Dn;
    const int dofs   = tx * 4;

    auto ldphi = [&](int hh, int ww) -> float4 {
        const int i = base_b + (hh * Wn + ww) * Dn + dofs;
        float4 p = *reinterpret_cast<const float4*>(pos + i);
        float4 n = *reinterpret_cast<const float4*>(neg + i);
        return make_float4(fmaf(-lam, n.x, p.x),
                           fmaf(-lam, n.y, p.y),
                           fmaf(-lam, n.z, p.z),
                           fmaf(-lam, n.w, p.w));
    };

    // prologue: Phi(h0-1) and Phi(h0) for this column
    const int hm0 = (h0 > 0) ? h0 - 1 : 0;
    float4 Cm = ldphi(hm0, w);
    float4 Cc = ldphi(h0,  w);

#pragma unroll 4
    for (int hh = 0; hh < CH; ++hh) {
        const int h  = h0 + hh;
        const int hp = (h < Hn - 1) ? h + 1 : Hn - 1;

        // three independent plane loads (hoistable, no barriers anywhere)
        float4 Cp = ldphi(hp, w);    // Phi(h+1, w)   — fresh stream
        float4 YM = ldphi(h,  wm);   // Phi(h, w-1)   — L1/L2 hit
        float4 YP = ldphi(h,  wp);   // Phi(h, w+1)   — L1/L2 hit

        // D-neighbors via warp shuffle (warp spans the full D row)
        float zm0 = __shfl_up_sync(0xffffffffu,  Cc.w, 1);
        float zp3 = __shfl_down_sync(0xffffffffu, Cc.x, 1);
        if (tx == 0)  zm0 = Cc.x;   // clamp d=0
        if (tx == 31) zp3 = Cc.w;   // clamp d=Dn-1

        const float c_[4]  = {Cc.x, Cc.y, Cc.z, Cc.w};
        const float xm_[4] = {Cm.x, Cm.y, Cm.z, Cm.w};
        const float xp_[4] = {Cp.x, Cp.y, Cp.z, Cp.w};
        const float ym_[4] = {YM.x, YM.y, YM.z, YM.w};
        const float yp_[4] = {YP.x, YP.y, YP.z, YP.w};
        const float zm_[4] = {zm0,  Cc.x, Cc.y, Cc.z};
        const float zp_[4] = {Cc.y, Cc.z, Cc.w, zp3};

        float r_[4];
#pragma unroll
        for (int j = 0; j < 4; ++j) {
            const float c  = c_[j];
            const float gx = (xp_[j] - xm_[j]) * 0.5f;
            const float gy = (yp_[j] - ym_[j]) * 0.5f;
            const float gz = (zp_[j] - zm_[j]) * 0.5f;
            const float grad_sq = fmaf(gx, gx, fmaf(gy, gy, gz * gz));
            const float lap = (xp_[j] + xm_[j]) + (yp_[j] + ym_[j])
                            + (zp_[j] + zm_[j]) - 6.0f * c;
            r_[j] = -2.0f * __expf(-2.0f * c) * fmaf(2.0f, grad_sq, lap);
        }

        // streaming store: don't let the write stream evict L2-resident inputs
        const int oidx = base_b + (h * Wn + w) * Dn + dofs;
        __stcs(reinterpret_cast<float4*>(out + oidx),
               make_float4(r_[0], r_[1], r_[2], r_[3]));

        Cm = Cc; Cc = Cp;
    }
}

extern "C" void kernel_launch(void* const* d_in, const int* in_sizes, int n_in,
                              void* d_out, int out_size)
{
    const float* pos = (const float*)d_in[0];  // phi_positive (B,H,W,D) f32
    const float* neg = (const float*)d_in[1];  // phi_negative (B,H,W,D) f32
    const float* lam = (const float*)d_in[2];  // lambda_repulsion (1,) f32
    float* out = (float*)d_out;

    dim3 block(32, WSLAB, 1);                   // 256 threads
    dim3 grid(Wn / WSLAB, Hn / CH, Bn);         // (16, 16, 4) = 1024 blocks
    conformal_march2<<<grid, block>>>(pos, neg, lam, out);
}

// round 4
// speedup vs baseline: 1.6091x; 1.1233x over previous
#include <cuda_runtime.h>

// ConformalMetric: R = -2*exp(-2*Phi) * (lap(Phi) + 2*|grad(Phi)|^2)
// Phi = phi_pos - lambda*phi_neg, edge-clamped 6-point stencil, h=1.
// Shape (B,H,W,D) = (4,128,128,128), D contiguous.
//
// Round-4: barrier-free H-march (round 3) + packed f32x2 math (FFMA2) +
// shorter blocks (CH=4) to shrink the wave-quantization tail.
// Vectors are loaded as ulonglong2 so each 64-bit half is directly a packed
// f32x2 operand: no pack cost on the load path.

#define Bn 4
#define Hn 128
#define Wn 128
#define Dn 128
#define WSLAB 8     // W rows per block
#define CH 4        // H planes marched per block

typedef unsigned long long u64;

__device__ __forceinline__ u64 pk2(float lo, float hi) {
    u64 r; asm("mov.b64 %0, {%1, %2};" : "=l"(r) : "f"(lo), "f"(hi)); return r;
}
__device__ __forceinline__ void upk2(u64 v, float& lo, float& hi) {
    asm("mov.b64 {%0, %1}, %2;" : "=f"(lo), "=f"(hi) : "l"(v));
}
__device__ __forceinline__ u64 fma2(u64 a, u64 b, u64 c) {
    u64 r; asm("fma.rn.f32x2 %0, %1, %2, %3;" : "=l"(r) : "l"(a), "l"(b), "l"(c)); return r;
}
__device__ __forceinline__ u64 add2(u64 a, u64 b) {
    u64 r; asm("add.rn.f32x2 %0, %1, %2;" : "=l"(r) : "l"(a), "l"(b)); return r;
}
__device__ __forceinline__ u64 mul2(u64 a, u64 b) {
    u64 r; asm("mul.rn.f32x2 %0, %1, %2;" : "=l"(r) : "l"(a), "l"(b)); return r;
}
__device__ __forceinline__ float ex2f(float x) {
    float r; asm("ex2.approx.f32 %0, %1;" : "=f"(r) : "f"(x)); return r;
}

struct P4 { u64 lo, hi; };   // 4 floats as two packed f32x2 (elems 0,1 | 2,3)

__global__ __launch_bounds__(256, 5) void conformal_pk(
    const float* __restrict__ pos,
    const float* __restrict__ neg,
    const float* __restrict__ lam_p,
    float* __restrict__ out)
{
    const float lam = __ldg(lam_p);
    const u64 NEGLAM = pk2(-lam, -lam);
    const u64 NEG1   = pk2(-1.0f, -1.0f);
    const u64 NEG6   = pk2(-6.0f, -6.0f);
    const u64 HALF   = pk2(0.5f, 0.5f);
    const u64 N2L2E  = pk2(-2.8853900817779268f, -2.8853900817779268f); // -2*log2(e)
    const u64 NEG2   = pk2(-2.0f, -2.0f);

    const int tx = threadIdx.x;            // 0..31 -> d4 lane
    const int ty = threadIdx.y;            // 0..WSLAB-1 -> w row
    const int b  = blockIdx.z;
    const int h0 = blockIdx.y * CH;
    const int w  = blockIdx.x * WSLAB + ty;

    const int wm = (w > 0)      ? w - 1 : 0;
    const int wp = (w < Wn - 1) ? w + 1 : Wn - 1;

    const int base_b = b * Hn * Wn * Dn;
    const int dofs   = tx * 4;

    auto ldphi = [&](int hh, int ww) -> P4 {
        const int i = base_b + (hh * Wn + ww) * Dn + dofs;
        const ulonglong2 P = *reinterpret_cast<const ulonglong2*>(pos + i);
        const ulonglong2 N = *reinterpret_cast<const ulonglong2*>(neg + i);
        P4 r;
        r.lo = fma2(N.x, NEGLAM, P.x);     // phi = pos - lam*neg (packed)
        r.hi = fma2(N.y, NEGLAM, P.y);
        return r;
    };

    // prologue: Phi(h0-1), Phi(h0)
    const int hm0 = (h0 > 0) ? h0 - 1 : 0;
    P4 Cm = ldphi(hm0, w);
    P4 Cc = ldphi(h0,  w);

#pragma unroll
    for (int hh = 0; hh < CH; ++hh) {
        const int h  = h0 + hh;
        const int hp = (h < Hn - 1) ? h + 1 : Hn - 1;

        // independent global loads (no barriers -> deep MLP)
        P4 Cp = ldphi(hp, w);    // Phi(h+1, w)
        P4 YM = ldphi(h,  wm);   // Phi(h, w-1) — L1/L2 hit
        P4 YP = ldphi(h,  wp);   // Phi(h, w+1) — L1/L2 hit

        // unpack center for shuffles / D-shifted pairs
        float cx, cy, cz, cw;
        upk2(Cc.lo, cx, cy);
        upk2(Cc.hi, cz, cw);

        float zm0 = __shfl_up_sync(0xffffffffu,  cw, 1);
        float zp3 = __shfl_down_sync(0xffffffffu, cx, 1);
        if (tx == 0)  zm0 = cx;   // clamp d=0
        if (tx == 31) zp3 = cw;   // clamp d=Dn-1

        // D-shifted packed vectors: zm={zm0,cx,cy,cz}, zp={cy,cz,cw,zp3}
        const u64 zm_lo = pk2(zm0, cx);
        const u64 mid   = pk2(cy, cz);     // shared: zm.hi == zp.lo
        const u64 zp_hi = pk2(cw, zp3);

        float r0, r1, r2, r3;
#pragma unroll
        for (int half = 0; half < 2; ++half) {
            const u64 c  = half ? Cc.hi : Cc.lo;
            const u64 xm = half ? Cm.hi : Cm.lo;
            const u64 xp = half ? Cp.hi : Cp.lo;
            const u64 ym = half ? YM.hi : YM.lo;
            const u64 yp = half ? YP.hi : YP.lo;
            const u64 zm = half ? mid   : zm_lo;
            const u64 zp = half ? zp_hi : mid;

            const u64 dx = fma2(xm, NEG1, xp);           // xp - xm
            const u64 dy = fma2(ym, NEG1, yp);
            const u64 dz = fma2(zm, NEG1, zp);
            u64 sq = mul2(dz, dz);
            sq = fma2(dy, dy, sq);
            sq = fma2(dx, dx, sq);                       // sum d^2 = 4*grad_sq

            u64 lap = add2(add2(add2(xp, xm), add2(yp, ym)), add2(zp, zm));
            lap = fma2(c, NEG6, lap);                    // - 6c
            const u64 arg  = fma2(sq, HALF, lap);        // lap + 2*grad_sq
            const u64 m    = mul2(c, N2L2E);             // -2c*log2(e)
            const u64 narg = mul2(arg, NEG2);            // -2*arg

            float m0, m1, a0, a1;
            upk2(m, m0, m1);
            upk2(narg, a0, a1);
            const float e0 = ex2f(m0);                   // exp(-2c)
            const float e1 = ex2f(m1);
            if (half) { r2 = e0 * a0; r3 = e1 * a1; }
            else      { r0 = e0 * a0; r1 = e1 * a1; }
        }

        const int oidx = base_b + (h * Wn + w) * Dn + dofs;
        __stcs(reinterpret_cast<float4*>(out + oidx),
               make_float4(r0, r1, r2, r3));

        Cm = Cc; Cc = Cp;
    }
}

extern "C" void kernel_launch(void* const* d_in, const int* in_sizes, int n_in,
                              void* d_out, int out_size)
{
    const float* pos = (const float*)d_in[0];  // phi_positive (B,H,W,D) f32
    const float* neg = (const float*)d_in[1];  // phi_negative (B,H,W,D) f32
    const float* lam = (const float*)d_in[2];  // lambda_repulsion (1,) f32
    float* out = (float*)d_out;

    dim3 block(32, WSLAB, 1);                   // 256 threads
    dim3 grid(Wn / WSLAB, Hn / CH, Bn);         // (16, 32, 4) = 2048 blocks
    conformal_pk<<<grid, block>>>(pos, neg, lam, out);
}